// round 2
// baseline (speedup 1.0000x reference)
#include <cuda_runtime.h>
#include <cuda_bf16.h>

#define NN 10000
#define EE 320000
#define DD 256
#define D4 64   // DD/4

// ---------------- scratch (__device__ globals; no allocation allowed) --------
__device__ float g_xw1[NN * DD];
__device__ float g_x1 [NN * DD];
__device__ float g_xw2[NN * DD];
__device__ int   g_indeg [NN];
__device__ int   g_cursor[NN];
__device__ int   g_csroff[NN + 1];
__device__ int   g_csrsrc[EE];
__device__ float g_dinv[NN];
__device__ float g_as[NN];
__device__ float g_ad[NN];

__device__ __forceinline__ float lrelu02(float x) {
    return x > 0.f ? x : 0.2f * x;
}

// ---------------- zero counters ---------------------------------------------
__global__ void zero_kernel() {
    int i = blockIdx.x * blockDim.x + threadIdx.x;
    if (i < NN) { g_indeg[i] = 0; g_cursor[i] = 0; }
}

// ---------------- count in-degree (real edges only) -------------------------
__global__ void count_kernel(const int* __restrict__ ei) {
    int e = blockIdx.x * blockDim.x + threadIdx.x;
    if (e < EE) atomicAdd(&g_indeg[ei[EE + e]], 1);
}

// ---------------- single-block exclusive scan + dinv ------------------------
__global__ void scan_kernel() {
    __shared__ int s[1024];
    __shared__ int carry_s;
    int t = threadIdx.x;
    if (t == 0) carry_s = 0;
    __syncthreads();
    for (int base = 0; base < NN; base += 1024) {
        int idx = base + t;
        int v = (idx < NN) ? g_indeg[idx] : 0;
        if (idx < NN) g_dinv[idx] = rsqrtf((float)(v + 1));  // +1 self loop
        s[t] = v;
        __syncthreads();
        #pragma unroll
        for (int off = 1; off < 1024; off <<= 1) {
            int x = (t >= off) ? s[t - off] : 0;
            __syncthreads();
            s[t] += x;
            __syncthreads();
        }
        if (idx < NN) g_csroff[idx] = carry_s + s[t] - v;
        int total = s[1023];
        __syncthreads();
        if (t == 0) carry_s += total;
        __syncthreads();
    }
    if (t == 0) g_csroff[NN] = carry_s;
}

// ---------------- scatter edges into CSR ------------------------------------
__global__ void fill_kernel(const int* __restrict__ ei) {
    int e = blockIdx.x * blockDim.x + threadIdx.x;
    if (e < EE) {
        int d   = ei[EE + e];
        int pos = g_csroff[d] + atomicAdd(&g_cursor[d], 1);
        g_csrsrc[pos] = ei[e];
    }
}

// ---------------- fp32 tiled GEMM: C[M,256] = A[M,256] @ B[256,256] ----------
#define BM 64
#define BN 64
#define BK 16
__device__ __forceinline__ void gemm_body(
    const float* __restrict__ A, const float* __restrict__ B,
    float* __restrict__ C, int M)
{
    __shared__ float As[BK][BM];
    __shared__ float Bs[BK][BN];
    int tid = threadIdx.x;
    int tx = tid & 15, ty = tid >> 4;
    int row0 = blockIdx.y * BM;
    int col0 = blockIdx.x * BN;
    float acc[4][4];
    #pragma unroll
    for (int i = 0; i < 4; i++)
        #pragma unroll
        for (int j = 0; j < 4; j++) acc[i][j] = 0.f;

    for (int k0 = 0; k0 < DD; k0 += BK) {
        {   // A tile: 64 rows x 16 k, one float4 per thread
            int r  = tid >> 2;
            int c4 = (tid & 3) << 2;
            float4 v = make_float4(0.f, 0.f, 0.f, 0.f);
            int gr = row0 + r;
            if (gr < M) v = *(const float4*)(A + (long)gr * DD + k0 + c4);
            As[c4 + 0][r] = v.x; As[c4 + 1][r] = v.y;
            As[c4 + 2][r] = v.z; As[c4 + 3][r] = v.w;
        }
        {   // B tile: 16 k x 64 cols
            int r  = tid >> 4;
            int c4 = (tid & 15) << 2;
            float4 v = *(const float4*)(B + (long)(k0 + r) * DD + col0 + c4);
            *(float4*)&Bs[r][c4] = v;
        }
        __syncthreads();
        #pragma unroll
        for (int k = 0; k < BK; k++) {
            float a[4], b[4];
            #pragma unroll
            for (int i = 0; i < 4; i++) a[i] = As[k][ty * 4 + i];
            #pragma unroll
            for (int j = 0; j < 4; j++) b[j] = Bs[k][tx * 4 + j];
            #pragma unroll
            for (int i = 0; i < 4; i++)
                #pragma unroll
                for (int j = 0; j < 4; j++) acc[i][j] += a[i] * b[j];
        }
        __syncthreads();
    }
    #pragma unroll
    for (int i = 0; i < 4; i++) {
        int gr = row0 + ty * 4 + i;
        if (gr < M) {
            float4 v = make_float4(acc[i][0], acc[i][1], acc[i][2], acc[i][3]);
            *(float4*)(C + (long)gr * DD + col0 + tx * 4) = v;
        }
    }
}

// Bind scratch buffers directly (no cudaGetSymbolAddress on host).
__global__ void __launch_bounds__(256) gemm1_kernel(
    const float* __restrict__ A, const float* __restrict__ B) {
    gemm_body(A, B, g_xw1, NN);
}
__global__ void __launch_bounds__(256) gemm2_kernel(
    const float* __restrict__ B) {
    gemm_body(g_x1, B, g_xw2, NN);
}

// ---------------- GCN aggregation: one block (64 thr) per dst node ----------
__global__ void __launch_bounds__(64) gcn_agg_kernel(const float* __restrict__ b1) {
    int i = blockIdx.x;
    int t = threadIdx.x;
    __shared__ int   sj[64];
    __shared__ float sw[64];
    float di = g_dinv[i];
    const float4* xw = (const float4*)g_xw1;
    float4 acc = xw[(long)i * D4 + t];            // self loop
    float wself = di * di;
    acc.x *= wself; acc.y *= wself; acc.z *= wself; acc.w *= wself;

    int beg = g_csroff[i], end = g_csroff[i + 1];
    for (int base = beg; base < end; base += 64) {
        int n = end - base; if (n > 64) n = 64;
        if (t < n) {
            int j = g_csrsrc[base + t];
            sj[t] = j;
            sw[t] = di * g_dinv[j];
        }
        __syncthreads();
        #pragma unroll 4
        for (int k = 0; k < n; k++) {
            float4 v = xw[(long)sj[k] * D4 + t];
            float w = sw[k];
            acc.x += v.x * w; acc.y += v.y * w;
            acc.z += v.z * w; acc.w += v.w * w;
        }
        __syncthreads();
    }
    float4 bb = ((const float4*)b1)[t];
    acc.x = fmaxf(acc.x + bb.x, 0.f);
    acc.y = fmaxf(acc.y + bb.y, 0.f);
    acc.z = fmaxf(acc.z + bb.z, 0.f);
    acc.w = fmaxf(acc.w + bb.w, 0.f);
    ((float4*)g_x1)[(long)i * D4 + t] = acc;
}

// ---------------- per-node attention dots: as = xw2·att_src, ad = xw2·att_dst
__global__ void node_dots_kernel(const float* __restrict__ att_src,
                                 const float* __restrict__ att_dst) {
    int warp = (blockIdx.x * blockDim.x + threadIdx.x) >> 5;
    int lane = threadIdx.x & 31;
    if (warp >= NN) return;
    const float* row = g_xw2 + (long)warp * DD;
    float s1 = 0.f, s2 = 0.f;
    #pragma unroll
    for (int k = 0; k < 8; k++) {
        float v = row[lane + k * 32];
        s1 += v * att_src[lane + k * 32];
        s2 += v * att_dst[lane + k * 32];
    }
    #pragma unroll
    for (int off = 16; off; off >>= 1) {
        s1 += __shfl_down_sync(0xffffffffu, s1, off);
        s2 += __shfl_down_sync(0xffffffffu, s2, off);
    }
    if (lane == 0) { g_as[warp] = s1; g_ad[warp] = s2; }
}

// ---------------- GAT aggregation: one block (64 thr) per dst node ----------
__global__ void __launch_bounds__(64) gat_agg_kernel(const float* __restrict__ b2,
                                                     float* __restrict__ out) {
    int i = blockIdx.x;
    int t = threadIdx.x;
    __shared__ float red[64];
    __shared__ int   sj[64];
    __shared__ float sw[64];

    float adi = g_ad[i];
    int beg = g_csroff[i], end = g_csroff[i + 1];
    float e_self = lrelu02(g_as[i] + adi);

    // pass 1a: max
    float lm = e_self;
    for (int e = beg + t; e < end; e += 64) {
        int j = g_csrsrc[e];
        lm = fmaxf(lm, lrelu02(g_as[j] + adi));
    }
    red[t] = lm; __syncthreads();
    #pragma unroll
    for (int off = 32; off; off >>= 1) {
        if (t < off) red[t] = fmaxf(red[t], red[t + off]);
        __syncthreads();
    }
    float m = red[0];
    __syncthreads();

    // pass 1b: sum of exp
    float ls = 0.f;
    for (int e = beg + t; e < end; e += 64) {
        int j = g_csrsrc[e];
        ls += __expf(lrelu02(g_as[j] + adi) - m);
    }
    red[t] = ls; __syncthreads();
    #pragma unroll
    for (int off = 32; off; off >>= 1) {
        if (t < off) red[t] += red[t + off];
        __syncthreads();
    }
    float ssum = red[0] + __expf(e_self - m);
    float inv = 1.f / (ssum + 1e-16f);
    __syncthreads();

    // pass 2: weighted aggregation
    const float4* xw = (const float4*)g_xw2;
    float4 acc = xw[(long)i * D4 + t];
    float aself = __expf(e_self - m) * inv;
    acc.x *= aself; acc.y *= aself; acc.z *= aself; acc.w *= aself;

    for (int base = beg; base < end; base += 64) {
        int n = end - base; if (n > 64) n = 64;
        if (t < n) {
            int j = g_csrsrc[base + t];
            sj[t] = j;
            sw[t] = __expf(lrelu02(g_as[j] + adi) - m) * inv;
        }
        __syncthreads();
        #pragma unroll 4
        for (int k = 0; k < n; k++) {
            float4 v = xw[(long)sj[k] * D4 + t];
            float w = sw[k];
            acc.x += v.x * w; acc.y += v.y * w;
            acc.z += v.z * w; acc.w += v.w * w;
        }
        __syncthreads();
    }
    float4 bb = ((const float4*)b2)[t];
    acc.x = fmaxf(acc.x + bb.x, 0.f);
    acc.y = fmaxf(acc.y + bb.y, 0.f);
    acc.z = fmaxf(acc.z + bb.z, 0.f);
    acc.w = fmaxf(acc.w + bb.w, 0.f);
    ((float4*)out)[(long)i * D4 + t] = acc;
}

// ---------------- launch ----------------------------------------------------
extern "C" void kernel_launch(void* const* d_in, const int* in_sizes, int n_in,
                              void* d_out, int out_size) {
    const float* event_emb = (const float*)d_in[0];
    const int*   edge_idx  = (const int*)  d_in[1];
    const float* W1        = (const float*)d_in[2];
    const float* b1        = (const float*)d_in[3];
    const float* W2        = (const float*)d_in[4];
    const float* att_src   = (const float*)d_in[5];
    const float* att_dst   = (const float*)d_in[6];
    const float* b2        = (const float*)d_in[7];
    float* out = (float*)d_out;

    // build CSR (by destination) — reused by both layers
    zero_kernel<<<(NN + 255) / 256, 256>>>();
    count_kernel<<<(EE + 255) / 256, 256>>>(edge_idx);
    scan_kernel<<<1, 1024>>>();
    fill_kernel<<<(EE + 255) / 256, 256>>>(edge_idx);

    dim3 ggrid(DD / BN, (NN + BM - 1) / BM);
    // layer 1: GCN
    gemm1_kernel<<<ggrid, 256>>>(event_emb, W1);
    gcn_agg_kernel<<<NN, 64>>>(b1);
    // layer 2: GAT
    gemm2_kernel<<<ggrid, 256>>>(W2);
    node_dots_kernel<<<(NN * 32 + 255) / 256, 256>>>(att_src, att_dst);
    gat_agg_kernel<<<NN, 64>>>(b2, out);
}

// round 3
// speedup vs baseline: 1.0211x; 1.0211x over previous
#include <cuda_runtime.h>
#include <cuda_bf16.h>

#define NN 10000
#define EE 320000
#define DD 256
#define D4 64   // DD/4

// ---------------- scratch (__device__ globals) ------------------------------
__device__ float g_xw1[NN * DD];
__device__ float g_x1 [NN * DD];
__device__ float g_xw2[NN * DD];
__device__ int   g_indeg [NN];
__device__ int   g_cursor[NN];
__device__ int   g_csroff[NN + 1];
__device__ int   g_csrsrc[EE];
__device__ float g_dinv[NN];
__device__ float g_as[NN];
__device__ float g_ad[NN];
__device__ float g_va[DD];   // W2 @ att_src
__device__ float g_vd[DD];   // W2 @ att_dst

__device__ __forceinline__ float lrelu02(float x) {
    return x > 0.f ? x : 0.2f * x;
}

// ---------------- prep: zero counters + va/vd matvec ------------------------
// 40 blocks x 256 thr. Blocks 0..31 also compute one row of va/vd per warp.
__global__ void __launch_bounds__(256) prep_kernel(
    const float* __restrict__ W2,
    const float* __restrict__ a_s, const float* __restrict__ a_d)
{
    int i = blockIdx.x * 256 + threadIdx.x;
    if (i < NN) { g_indeg[i] = 0; g_cursor[i] = 0; }

    int w = threadIdx.x >> 5, l = threadIdx.x & 31;
    int row = blockIdx.x * 8 + w;
    if (row < DD) {
        float s1 = 0.f, s2 = 0.f;
        #pragma unroll
        for (int k = 0; k < 8; k++) {
            float v = W2[row * DD + l + k * 32];
            s1 += v * a_s[l + k * 32];
            s2 += v * a_d[l + k * 32];
        }
        #pragma unroll
        for (int off = 16; off; off >>= 1) {
            s1 += __shfl_down_sync(0xffffffffu, s1, off);
            s2 += __shfl_down_sync(0xffffffffu, s2, off);
        }
        if (l == 0) { g_va[row] = s1; g_vd[row] = s2; }
    }
}

// ---------------- count in-degree, 4 edges/thread ---------------------------
__global__ void count_kernel(const int* __restrict__ ei) {
    int e4 = (blockIdx.x * blockDim.x + threadIdx.x) * 4;
    if (e4 < EE) {
        int4 d = *(const int4*)(ei + EE + e4);
        atomicAdd(&g_indeg[d.x], 1);
        atomicAdd(&g_indeg[d.y], 1);
        atomicAdd(&g_indeg[d.z], 1);
        atomicAdd(&g_indeg[d.w], 1);
    }
}

// ---------------- single-block exclusive scan + dinv ------------------------
__global__ void scan_kernel() {
    __shared__ int s[1024];
    __shared__ int carry_s;
    int t = threadIdx.x;
    if (t == 0) carry_s = 0;
    __syncthreads();
    for (int base = 0; base < NN; base += 1024) {
        int idx = base + t;
        int v = (idx < NN) ? g_indeg[idx] : 0;
        if (idx < NN) g_dinv[idx] = rsqrtf((float)(v + 1));  // +1 self loop
        s[t] = v;
        __syncthreads();
        #pragma unroll
        for (int off = 1; off < 1024; off <<= 1) {
            int x = (t >= off) ? s[t - off] : 0;
            __syncthreads();
            s[t] += x;
            __syncthreads();
        }
        if (idx < NN) g_csroff[idx] = carry_s + s[t] - v;
        int total = s[1023];
        __syncthreads();
        if (t == 0) carry_s += total;
        __syncthreads();
    }
    if (t == 0) g_csroff[NN] = carry_s;
}

// ---------------- scatter edges into CSR, 4 edges/thread --------------------
__global__ void fill_kernel(const int* __restrict__ ei) {
    int e4 = (blockIdx.x * blockDim.x + threadIdx.x) * 4;
    if (e4 < EE) {
        int4 sv = *(const int4*)(ei + e4);
        int4 dv = *(const int4*)(ei + EE + e4);
        int p0 = g_csroff[dv.x] + atomicAdd(&g_cursor[dv.x], 1);
        int p1 = g_csroff[dv.y] + atomicAdd(&g_cursor[dv.y], 1);
        int p2 = g_csroff[dv.z] + atomicAdd(&g_cursor[dv.z], 1);
        int p3 = g_csroff[dv.w] + atomicAdd(&g_cursor[dv.w], 1);
        g_csrsrc[p0] = sv.x;
        g_csrsrc[p1] = sv.y;
        g_csrsrc[p2] = sv.z;
        g_csrsrc[p3] = sv.w;
    }
}

// ---------------- fp32 GEMM: C[M,256] = A[M,256] @ B[256,256] ---------------
// 128x64x16 tiles, 256 threads, 8x4 per-thread accum, double-buffered smem.
#define BM 128
#define BN 64
#define BK 16

__device__ __forceinline__ float4 ldA4(const float* __restrict__ A,
                                       int r, int c, int M) {
    if (r < M) return *(const float4*)(A + (long)r * DD + c);
    return make_float4(0.f, 0.f, 0.f, 0.f);
}

__device__ __forceinline__ void gemm_body(
    const float* __restrict__ A, const float* __restrict__ B,
    float* __restrict__ C, int M)
{
    __shared__ float As[2][BK][BM];
    __shared__ float Bs[2][BK][BN];
    int t  = threadIdx.x;
    int tx = t & 15, ty = t >> 4;
    int row0 = blockIdx.y * BM, col0 = blockIdx.x * BN;

    float acc[8][4];
    #pragma unroll
    for (int i = 0; i < 8; i++)
        #pragma unroll
        for (int j = 0; j < 4; j++) acc[i][j] = 0.f;

    // loader coordinates
    int ar = t >> 2;             // 0..63 (row within half-tile)
    int ac = (t & 3) << 2;       // 0,4,8,12
    int br = t >> 4;             // 0..15
    int bc = (t & 15) << 2;      // 0..60

    // prologue: tile 0
    float4 a0 = ldA4(A, row0 + ar,      ac, M);
    float4 a1 = ldA4(A, row0 + ar + 64, ac, M);
    float4 b0 = *(const float4*)(B + (long)br * DD + col0 + bc);
    As[0][ac + 0][ar] = a0.x; As[0][ac + 1][ar] = a0.y;
    As[0][ac + 2][ar] = a0.z; As[0][ac + 3][ar] = a0.w;
    As[0][ac + 0][ar + 64] = a1.x; As[0][ac + 1][ar + 64] = a1.y;
    As[0][ac + 2][ar + 64] = a1.z; As[0][ac + 3][ar + 64] = a1.w;
    *(float4*)&Bs[0][br][bc] = b0;
    __syncthreads();

    int buf = 0;
    #pragma unroll 1
    for (int kt = 0; kt < DD / BK; kt++) {
        float4 na0, na1, nb0;
        if (kt < DD / BK - 1) {
            int k0 = (kt + 1) * BK;
            na0 = ldA4(A, row0 + ar,      k0 + ac, M);
            na1 = ldA4(A, row0 + ar + 64, k0 + ac, M);
            nb0 = *(const float4*)(B + (long)(k0 + br) * DD + col0 + bc);
        }
        #pragma unroll
        for (int k = 0; k < BK; k++) {
            float4 av0 = *(float4*)&As[buf][k][ty * 8];
            float4 av1 = *(float4*)&As[buf][k][ty * 8 + 4];
            float4 bv  = *(float4*)&Bs[buf][k][tx * 4];
            float a[8] = {av0.x, av0.y, av0.z, av0.w, av1.x, av1.y, av1.z, av1.w};
            float b[4] = {bv.x, bv.y, bv.z, bv.w};
            #pragma unroll
            for (int i = 0; i < 8; i++)
                #pragma unroll
                for (int j = 0; j < 4; j++) acc[i][j] += a[i] * b[j];
        }
        if (kt < DD / BK - 1) {
            int nb = buf ^ 1;
            As[nb][ac + 0][ar] = na0.x; As[nb][ac + 1][ar] = na0.y;
            As[nb][ac + 2][ar] = na0.z; As[nb][ac + 3][ar] = na0.w;
            As[nb][ac + 0][ar + 64] = na1.x; As[nb][ac + 1][ar + 64] = na1.y;
            As[nb][ac + 2][ar + 64] = na1.z; As[nb][ac + 3][ar + 64] = na1.w;
            *(float4*)&Bs[nb][br][bc] = nb0;
            __syncthreads();
            buf = nb;
        }
    }
    #pragma unroll
    for (int i = 0; i < 8; i++) {
        int gr = row0 + ty * 8 + i;
        if (gr < M) {
            float4 v = make_float4(acc[i][0], acc[i][1], acc[i][2], acc[i][3]);
            *(float4*)(C + (long)gr * DD + col0 + tx * 4) = v;
        }
    }
}

__global__ void __launch_bounds__(256) gemm1_kernel(
    const float* __restrict__ A, const float* __restrict__ B) {
    gemm_body(A, B, g_xw1, NN);
}
__global__ void __launch_bounds__(256) gemm2_kernel(
    const float* __restrict__ B) {
    gemm_body(g_x1, B, g_xw2, NN);
}

// ---------------- GCN aggregation + fused attention dots --------------------
__global__ void __launch_bounds__(64) gcn_agg_kernel(const float* __restrict__ b1) {
    int i = blockIdx.x;
    int t = threadIdx.x;
    __shared__ int   sj[64];
    __shared__ float sw[64];
    __shared__ float rs[64], rd[64];

    float di = g_dinv[i];
    const float4* xw = (const float4*)g_xw1;
    float4 acc = xw[(long)i * D4 + t];            // self loop
    float wself = di * di;
    acc.x *= wself; acc.y *= wself; acc.z *= wself; acc.w *= wself;

    int beg = g_csroff[i], end = g_csroff[i + 1];
    for (int base = beg; base < end; base += 64) {
        int n = end - base; if (n > 64) n = 64;
        if (t < n) {
            int j = g_csrsrc[base + t];
            sj[t] = j;
            sw[t] = di * g_dinv[j];
        }
        __syncthreads();
        #pragma unroll 4
        for (int k = 0; k < n; k++) {
            float4 v = xw[(long)sj[k] * D4 + t];
            float w = sw[k];
            acc.x += v.x * w; acc.y += v.y * w;
            acc.z += v.z * w; acc.w += v.w * w;
        }
        __syncthreads();
    }
    float4 bb = ((const float4*)b1)[t];
    acc.x = fmaxf(acc.x + bb.x, 0.f);
    acc.y = fmaxf(acc.y + bb.y, 0.f);
    acc.z = fmaxf(acc.z + bb.z, 0.f);
    acc.w = fmaxf(acc.w + bb.w, 0.f);
    ((float4*)g_x1)[(long)i * D4 + t] = acc;

    // fused attention dots: as_i = x1_i . va, ad_i = x1_i . vd
    float4 va = ((const float4*)g_va)[t];
    float4 vd = ((const float4*)g_vd)[t];
    float ds = acc.x * va.x + acc.y * va.y + acc.z * va.z + acc.w * va.w;
    float dd = acc.x * vd.x + acc.y * vd.y + acc.z * vd.z + acc.w * vd.w;
    rs[t] = ds; rd[t] = dd;
    __syncthreads();
    #pragma unroll
    for (int off = 32; off; off >>= 1) {
        if (t < off) { rs[t] += rs[t + off]; rd[t] += rd[t + off]; }
        __syncthreads();
    }
    if (t == 0) { g_as[i] = rs[0]; g_ad[i] = rd[0]; }
}

// ---------------- GAT aggregation: one block (64 thr) per dst node ----------
__global__ void __launch_bounds__(64) gat_agg_kernel(const float* __restrict__ b2,
                                                     float* __restrict__ out) {
    int i = blockIdx.x;
    int t = threadIdx.x;
    __shared__ float red[64];
    __shared__ int   sj[64];
    __shared__ float sw[64];

    float adi = g_ad[i];
    int beg = g_csroff[i], end = g_csroff[i + 1];
    float e_self = lrelu02(g_as[i] + adi);

    // pass 1a: max
    float lm = e_self;
    for (int e = beg + t; e < end; e += 64) {
        int j = g_csrsrc[e];
        lm = fmaxf(lm, lrelu02(g_as[j] + adi));
    }
    red[t] = lm; __syncthreads();
    #pragma unroll
    for (int off = 32; off; off >>= 1) {
        if (t < off) red[t] = fmaxf(red[t], red[t + off]);
        __syncthreads();
    }
    float m = red[0];
    __syncthreads();

    // pass 1b: sum of exp
    float ls = 0.f;
    for (int e = beg + t; e < end; e += 64) {
        int j = g_csrsrc[e];
        ls += __expf(lrelu02(g_as[j] + adi) - m);
    }
    red[t] = ls; __syncthreads();
    #pragma unroll
    for (int off = 32; off; off >>= 1) {
        if (t < off) red[t] += red[t + off];
        __syncthreads();
    }
    float ssum = red[0] + __expf(e_self - m);
    float inv = 1.f / (ssum + 1e-16f);
    __syncthreads();

    // pass 2: weighted aggregation
    const float4* xw = (const float4*)g_xw2;
    float4 acc = xw[(long)i * D4 + t];
    float aself = __expf(e_self - m) * inv;
    acc.x *= aself; acc.y *= aself; acc.z *= aself; acc.w *= aself;

    for (int base = beg; base < end; base += 64) {
        int n = end - base; if (n > 64) n = 64;
        if (t < n) {
            int j = g_csrsrc[base + t];
            sj[t] = j;
            sw[t] = __expf(lrelu02(g_as[j] + adi) - m) * inv;
        }
        __syncthreads();
        #pragma unroll 4
        for (int k = 0; k < n; k++) {
            float4 v = xw[(long)sj[k] * D4 + t];
            float w = sw[k];
            acc.x += v.x * w; acc.y += v.y * w;
            acc.z += v.z * w; acc.w += v.w * w;
        }
        __syncthreads();
    }
    float4 bb = ((const float4*)b2)[t];
    acc.x = fmaxf(acc.x + bb.x, 0.f);
    acc.y = fmaxf(acc.y + bb.y, 0.f);
    acc.z = fmaxf(acc.z + bb.z, 0.f);
    acc.w = fmaxf(acc.w + bb.w, 0.f);
    ((float4*)out)[(long)i * D4 + t] = acc;
}

// ---------------- launch ----------------------------------------------------
extern "C" void kernel_launch(void* const* d_in, const int* in_sizes, int n_in,
                              void* d_out, int out_size) {
    const float* event_emb = (const float*)d_in[0];
    const int*   edge_idx  = (const int*)  d_in[1];
    const float* W1        = (const float*)d_in[2];
    const float* b1        = (const float*)d_in[3];
    const float* W2        = (const float*)d_in[4];
    const float* att_src   = (const float*)d_in[5];
    const float* att_dst   = (const float*)d_in[6];
    const float* b2        = (const float*)d_in[7];
    float* out = (float*)d_out;

    // CSR build (by destination) + va/vd precompute
    prep_kernel<<<40, 256>>>(W2, att_src, att_dst);
    count_kernel<<<(EE / 4 + 255) / 256, 256>>>(edge_idx);
    scan_kernel<<<1, 1024>>>();
    fill_kernel<<<(EE / 4 + 255) / 256, 256>>>(edge_idx);

    dim3 ggrid(DD / BN, (NN + BM - 1) / BM);
    // layer 1: GCN
    gemm1_kernel<<<ggrid, 256>>>(event_emb, W1);
    gcn_agg_kernel<<<NN, 64>>>(b1);
    // layer 2: GAT
    gemm2_kernel<<<ggrid, 256>>>(W2);
    gat_agg_kernel<<<NN, 64>>>(b2, out);
}